// round 17
// baseline (speedup 1.0000x reference)
#include <cuda_runtime.h>
#include <cuda_fp16.h>
#include <cuda_bf16.h>
#include <math.h>
#include <stdint.h>

// Problem constants
#define BATCH 32
#define SEQ   2048
#define HID   1024
#define KDIM  3072          // 3*HID
#define MROWS (BATCH*SEQ)   // 65536

// Scratch (device globals: allocation-free rule)
__device__ float  g_w[BATCH * SEQ];            // softmax weights
__device__ float  g_pp[8][BATCH * KDIM];       // pooled-trg partials (8 L-splits)
__device__ float  g_p[BATCH * KDIM];           // reduced pooled trg
__device__ float  g_np[8][MROWS];              // per-n-tile rowsq partials
__device__ __half g_wh[(size_t)HID * KDIM];    // fp16 W (6 MB)

// ---------------------------------------------------------------------------
// helpers
// ---------------------------------------------------------------------------
__device__ __forceinline__ uint32_t smem_u32(const void* p) {
    uint32_t a;
    asm("{ .reg .u64 t; cvta.to.shared.u64 t, %1; cvt.u32.u64 %0, t; }"
        : "=r"(a) : "l"(p));
    return a;
}

__device__ __forceinline__ void cp16(uint32_t saddr, const void* gaddr) {
    asm volatile("cp.async.cg.shared.global [%0], [%1], 16;"
                 :: "r"(saddr), "l"(gaddr) : "memory");
}

__device__ __forceinline__ void ldsm_x4(uint32_t& r0, uint32_t& r1,
                                        uint32_t& r2, uint32_t& r3, uint32_t addr) {
    asm volatile("ldmatrix.sync.aligned.m8n8.x4.shared.b16 {%0,%1,%2,%3}, [%4];"
                 : "=r"(r0), "=r"(r1), "=r"(r2), "=r"(r3) : "r"(addr));
}

__device__ __forceinline__ uint32_t lds_f32x2_pack(uint32_t addr) {
    float x, y;
    asm volatile("ld.shared.v2.f32 {%0,%1}, [%2];" : "=f"(x), "=f"(y) : "r"(addr));
    __half2 h = __floats2half2_rn(x, y);
    return *(uint32_t*)&h;
}

__device__ __forceinline__ void mma_f16(float& d0, float& d1, float& d2, float& d3,
                                        uint32_t a0, uint32_t a1, uint32_t a2, uint32_t a3,
                                        uint32_t b0, uint32_t b1) {
    asm volatile(
        "mma.sync.aligned.m16n8k16.row.col.f32.f16.f16.f32 "
        "{%0,%1,%2,%3}, {%4,%5,%6,%7}, {%8,%9}, {%0,%1,%2,%3};"
        : "+f"(d0), "+f"(d1), "+f"(d2), "+f"(d3)
        : "r"(a0), "r"(a1), "r"(a2), "r"(a3), "r"(b0), "r"(b1));
}

// ---------------------------------------------------------------------------
// Kernel 0: fp32 -> fp16 conversion (W only; trg conversion is fused in norm)
// ---------------------------------------------------------------------------
__global__ __launch_bounds__(256)
void k_cvt8(const float* __restrict__ in, __half* __restrict__ out)
{
    const size_t i = ((size_t)blockIdx.x * 256 + threadIdx.x) * 8;
    float4 v0 = *(const float4*)(in + i);
    float4 v1 = *(const float4*)(in + i + 4);
    __half2 h0 = __floats2half2_rn(v0.x, v0.y);
    __half2 h1 = __floats2half2_rn(v0.z, v0.w);
    __half2 h2 = __floats2half2_rn(v1.x, v1.y);
    __half2 h3 = __floats2half2_rn(v1.z, v1.w);
    uint4 u;
    u.x = *(uint32_t*)&h0; u.y = *(uint32_t*)&h1;
    u.z = *(uint32_t*)&h2; u.w = *(uint32_t*)&h3;
    *(uint4*)(out + i) = u;
}

// ---------------------------------------------------------------------------
// Kernel 1: partial rowsq for one 128x128 output tile, full K.
// A path: fp32 via cp.async (NO pre-conversion pass); fragments loaded as
//   ld.shared.v2.f32 + cvt-pack to half2 (identical rounding to k_cvt8, so
//   norm1 is bit-identical to the pre-converted version).
// B path: fp16 W via cp.async + ldmatrix (unchanged).
// 128 threads = 4 warps, warp grid 2x2, warp tile 64x64, 2 CTAs/SM
// (256 regs/thread available). A-tile swizzle: 16B chunk c -> c ^ 2*(row&7)
// (conflict-free LDS.64 within 16-lane phases). Double-buffered, BK=64.
// grid (8 n-tiles, 512 m-blocks).
// ---------------------------------------------------------------------------
#define BKH    64                              // k elements per stage
#define A_TILE 32768                           // 128 rows x 256B (fp32)
#define B_TILE 16384                           // 128 rows x 128B (fp16)
#define SMEM_NORM (2 * A_TILE + 2 * B_TILE)    // 96 KB
#define NSTG   (KDIM / BKH)                    // 48

__global__ __launch_bounds__(128, 2)
void k_norm_f32a(const float* __restrict__ trg, const float* __restrict__ bias)
{
    extern __shared__ __align__(128) char smem[];
    const uint32_t sb = smem_u32(smem);
    const uint32_t sA[2] = { sb,              sb + A_TILE };
    const uint32_t sB[2] = { sb + 2*A_TILE,   sb + 2*A_TILE + B_TILE };

    __shared__ float rowsq_s[128][2];

    const int tid  = threadIdx.x;
    const int lane = tid & 31;
    const int w    = tid >> 5;                // 0..3
    const int wy   = w >> 1;                  // 0..1  (M)
    const int wx   = w & 1;                   // 0..1  (N)
    const int g    = lane >> 2;               // 0..7  (MMA group)
    const int tig  = lane & 3;                // 0..3
    const int WM   = wy * 64;
    const int WN   = wx * 64;
    const int    nx = blockIdx.x;             // n-tile 0..7
    const int    n0 = nx * 128;
    const size_t m0 = (size_t)blockIdx.y * 128;

    // ---- A cp.async: 2048 16B-chunks (4 floats), 16 per thread ----
    const int ac        = tid & 15;           // chunk in row (constant)
    const int arow_base = tid >> 4;           // 0..7; rows = arow_base + i*8
    const uint32_t a_sw = (uint32_t)((ac ^ (2 * arow_base)) << 4);

    // ---- B cp.async: 1024 16B-chunks, 8 per thread ----
    const int lc    = tid & 7;
    const int lcol8 = lc * 8;
    int brow[8], bsoff[8];
    #pragma unroll
    for (int i = 0; i < 8; ++i) {
        brow[i]  = (tid + i * 128) >> 3;
        bsoff[i] = brow[i] * 128 + ((lc ^ (brow[i] & 7)) << 4);
    }

    const float*  gA = trg + m0 * (size_t)KDIM;
    const __half* gB = g_wh + (size_t)n0 * KDIM;

    // ---- B ldmatrix per-lane row bases ----
    const int sub  = ((lane >> 3) & 1) * 8 + (lane & 7);
    const int hi   = (lane >> 4) & 1;
    const int mod7 = lane & 7;
    int boff[4];
    #pragma unroll
    for (int j = 0; j < 4; ++j) boff[j] = (WN + j*16 + sub) * 128;

    // ---- A scalar-load bases: row = WM + mt*16 + h*8 + g ----
    // row & 7 == g  (WM, mt*16, h*8 all multiples of 8)
    const uint32_t a_lane_base = (uint32_t)(g * 256 + (tig & 1) * 8);
    const int t2 = tig >> 1;
    const int gx2 = g * 2;                    // XOR term (2*(row&7)) = 2g

    float acc[4][8][4];
    #pragma unroll
    for (int mt = 0; mt < 4; ++mt)
        #pragma unroll
        for (int nt = 0; nt < 8; ++nt)
            #pragma unroll
            for (int c = 0; c < 4; ++c) acc[mt][nt][c] = 0.f;

    // prologue: stage 0
    #pragma unroll
    for (int i = 0; i < 16; ++i) {
        const int row = arow_base + i * 8;
        cp16(sA[0] + (uint32_t)(row * 256) + a_sw,
             gA + (size_t)row * KDIM + ac * 4);
    }
    #pragma unroll
    for (int i = 0; i < 8; ++i)
        cp16(sB[0] + bsoff[i], gB + (size_t)brow[i] * KDIM + lcol8);
    asm volatile("cp.async.commit_group;" ::: "memory");

    for (int s = 0; s < NSTG; ++s) {
        const int buf = s & 1;
        if (s + 1 < NSTG) {
            const int nb = buf ^ 1;
            const int k1 = (s + 1) * BKH;
            #pragma unroll
            for (int i = 0; i < 16; ++i) {
                const int row = arow_base + i * 8;
                cp16(sA[nb] + (uint32_t)(row * 256) + a_sw,
                     gA + (size_t)row * KDIM + k1 + ac * 4);
            }
            #pragma unroll
            for (int i = 0; i < 8; ++i)
                cp16(sB[nb] + bsoff[i], gB + (size_t)brow[i] * KDIM + k1 + lcol8);
            asm volatile("cp.async.commit_group;" ::: "memory");
            asm volatile("cp.async.wait_group 1;" ::: "memory");
        } else {
            asm volatile("cp.async.wait_group 0;" ::: "memory");
        }
        __syncthreads();

        const uint32_t bA = sA[buf] + a_lane_base;
        const uint32_t bB = sB[buf];
        #pragma unroll
        for (int ks = 0; ks < BKH / 16; ++ks) {
            // A fragments: fp32 pairs -> half2 (rounding == k_cvt8)
            const uint32_t swlo = (uint32_t)((((ks*4) | t2) ^ gx2) << 4);
            const uint32_t swhi = (uint32_t)((((ks*4) | (t2 | 2)) ^ gx2) << 4);
            uint32_t af[4][4], bf[8][2];
            #pragma unroll
            for (int mt = 0; mt < 4; ++mt) {
                const uint32_t r0 = bA + (uint32_t)((WM + mt*16) * 256);
                const uint32_t r1 = r0 + 8 * 256;
                af[mt][0] = lds_f32x2_pack(r0 + swlo);
                af[mt][1] = lds_f32x2_pack(r1 + swlo);
                af[mt][2] = lds_f32x2_pack(r0 + swhi);
                af[mt][3] = lds_f32x2_pack(r1 + swhi);
            }
            const uint32_t swb = (uint32_t)(((ks*2 + hi) ^ mod7) << 4);
            #pragma unroll
            for (int j = 0; j < 4; ++j)
                ldsm_x4(bf[2*j][0], bf[2*j+1][0], bf[2*j][1], bf[2*j+1][1],
                        bB + boff[j] + swb);
            #pragma unroll
            for (int mt = 0; mt < 4; ++mt)
                #pragma unroll
                for (int nt = 0; nt < 8; ++nt)
                    mma_f16(acc[mt][nt][0], acc[mt][nt][1],
                            acc[mt][nt][2], acc[mt][nt][3],
                            af[mt][0], af[mt][1], af[mt][2], af[mt][3],
                            bf[nt][0], bf[nt][1]);
        }
        __syncthreads();
    }

    // epilogue: +bias, square-accumulate per row (partial over this n-tile)
    float rowsq[8];
    #pragma unroll
    for (int i = 0; i < 8; ++i) rowsq[i] = 0.f;
    #pragma unroll
    for (int nt = 0; nt < 8; ++nt) {
        const int cb = n0 + WN + nt*8 + 2*tig;
        const float b0 = __ldg(bias + cb);
        const float b1 = __ldg(bias + cb + 1);
        #pragma unroll
        for (int mt = 0; mt < 4; ++mt) {
            float v0 = acc[mt][nt][0] + b0;
            float v1 = acc[mt][nt][1] + b1;
            float v2 = acc[mt][nt][2] + b0;
            float v3 = acc[mt][nt][3] + b1;
            rowsq[mt*2+0] = fmaf(v0, v0, rowsq[mt*2+0]);
            rowsq[mt*2+0] = fmaf(v1, v1, rowsq[mt*2+0]);
            rowsq[mt*2+1] = fmaf(v2, v2, rowsq[mt*2+1]);
            rowsq[mt*2+1] = fmaf(v3, v3, rowsq[mt*2+1]);
        }
    }
    #pragma unroll
    for (int i = 0; i < 8; ++i) {
        rowsq[i] += __shfl_xor_sync(0xffffffffu, rowsq[i], 1);
        rowsq[i] += __shfl_xor_sync(0xffffffffu, rowsq[i], 2);
    }
    if (tig == 0) {
        #pragma unroll
        for (int mt = 0; mt < 4; ++mt)
            #pragma unroll
            for (int i = 0; i < 2; ++i)
                rowsq_s[WM + mt*16 + i*8 + g][wx] = rowsq[mt*2 + i];
    }
    __syncthreads();
    g_np[nx][m0 + tid] = rowsq_s[tid][0] + rowsq_s[tid][1];
}

// ---------------------------------------------------------------------------
// Kernel 2: combine rowsq partials -> norm1, then softmax over L -> g_w
// ---------------------------------------------------------------------------
__global__ void k_softmax(float* __restrict__ norm1)
{
    const int b = blockIdx.x;
    const int tid = threadIdx.x;
    __shared__ float red[256];

    for (int l = tid; l < SEQ; l += 256) {
        const int m = b * SEQ + l;
        float s = 0.f;
        #pragma unroll
        for (int j = 0; j < 8; ++j) s += g_np[j][m];
        norm1[m] = sqrtf(s);
    }
    __syncthreads();

    const float* x = norm1 + b * SEQ;
    float m = -1e30f;
    for (int l = tid; l < SEQ; l += 256) m = fmaxf(m, x[l]);
    red[tid] = m; __syncthreads();
    for (int s = 128; s > 0; s >>= 1) {
        if (tid < s) red[tid] = fmaxf(red[tid], red[tid + s]);
        __syncthreads();
    }
    float bm = red[0];
    __syncthreads();

    float sum = 0.0f;
    for (int l = tid; l < SEQ; l += 256) {
        float e = __expf(x[l] - bm);
        g_w[b * SEQ + l] = e;
        sum += e;
    }
    red[tid] = sum; __syncthreads();
    for (int s = 128; s > 0; s >>= 1) {
        if (tid < s) red[tid] += red[tid + s];
        __syncthreads();
    }
    float inv = 1.0f / red[0];
    for (int l = tid; l < SEQ; l += 256) g_w[b * SEQ + l] *= inv;
}

// ---------------------------------------------------------------------------
// Kernel 3: pooled partials from fp32 trg: g_pp[ls][b,k] = sum w[b,l]*trg[b,l,k]
// ---------------------------------------------------------------------------
__global__ void k_pool(const float* __restrict__ trg)
{
    const int kc = blockIdx.x;            // 0..2
    const int ls = blockIdx.y;            // 0..7
    const int b  = blockIdx.z;            // 0..31
    const int tid = threadIdx.x;
    const int k0 = kc * 1024 + tid * 4;

    const float* base = trg + (size_t)b * SEQ * KDIM;
    float4 acc = make_float4(0.f, 0.f, 0.f, 0.f);

    const int l0 = ls * 256;
    #pragma unroll 4
    for (int l = l0; l < l0 + 256; ++l) {
        float wl = g_w[b * SEQ + l];
        float4 v = *(const float4*)(base + (size_t)l * KDIM + k0);
        acc.x = fmaf(wl, v.x, acc.x);
        acc.y = fmaf(wl, v.y, acc.y);
        acc.z = fmaf(wl, v.z, acc.z);
        acc.w = fmaf(wl, v.w, acc.w);
    }
    *(float4*)(&g_pp[ls][b * KDIM + k0]) = acc;
}

// ---------------------------------------------------------------------------
// Kernel 3b: reduce the 8 pooled partials -> g_p
// ---------------------------------------------------------------------------
__global__ __launch_bounds__(256)
void k_red(void)
{
    const int i = blockIdx.x * 256 + threadIdx.x;   // 0 .. BATCH*KDIM-1
    float s = 0.f;
    #pragma unroll
    for (int l = 0; l < 8; ++l) s += g_pp[l][i];
    g_p[i] = s;
}

// ---------------------------------------------------------------------------
// Kernel 4: summ[b,h] = g_p[b,:] . W[h,:] + bias[h]   (fp16 W, fp32 accum)
// ---------------------------------------------------------------------------
__global__ void k_out(const float* __restrict__ bias, float* __restrict__ summ)
{
    const int b = blockIdx.y;
    const int tid = threadIdx.x;
    const int lane = tid & 31;
    const int wid = tid >> 5;

    __shared__ float ps[KDIM];
    for (int k = tid; k < KDIM; k += 256)
        ps[k] = g_p[b * KDIM + k];
    __syncthreads();

    const int h = blockIdx.x * 8 + wid;
    const __half* wr = g_wh + (size_t)h * KDIM;
    float s = 0.0f;
    for (int k = lane * 8; k < KDIM; k += 256) {
        uint4 u = *(const uint4*)(wr + k);
        float2 w0 = __half22float2(*(__half2*)&u.x);
        float2 w1 = __half22float2(*(__half2*)&u.y);
        float2 w2 = __half22float2(*(__half2*)&u.z);
        float2 w3 = __half22float2(*(__half2*)&u.w);
        float4 p0 = *(const float4*)(ps + k);
        float4 p1 = *(const float4*)(ps + k + 4);
        s = fmaf(w0.x, p0.x, s); s = fmaf(w0.y, p0.y, s);
        s = fmaf(w1.x, p0.z, s); s = fmaf(w1.y, p0.w, s);
        s = fmaf(w2.x, p1.x, s); s = fmaf(w2.y, p1.y, s);
        s = fmaf(w3.x, p1.z, s); s = fmaf(w3.y, p1.w, s);
    }
    #pragma unroll
    for (int o = 16; o > 0; o >>= 1) s += __shfl_xor_sync(0xffffffffu, s, o);
    if (lane == 0) summ[b * HID + h] = s + bias[h];
}

// ---------------------------------------------------------------------------
extern "C" void kernel_launch(void* const* d_in, const int* in_sizes, int n_in,
                              void* d_out, int out_size)
{
    const float* trg  = (const float*)d_in[0];
    // d_in[1] = src (unused, n_layers == 0)
    const float* W    = (const float*)d_in[2];
    const float* bias = (const float*)d_in[3];

    float* out   = (float*)d_out;
    float* summ  = out;                   // [32, 1024]
    float* norm1 = out + BATCH * HID;     // [32, 2048]

    __half* wh; cudaGetSymbolAddress((void**)&wh, g_wh);

    cudaFuncSetAttribute(k_norm_f32a, cudaFuncAttributeMaxDynamicSharedMemorySize, SMEM_NORM);

    k_cvt8<<<(HID * KDIM) / (256 * 8), 256>>>(W, wh);
    k_norm_f32a<<<dim3(8, MROWS / 128), 128, SMEM_NORM>>>(trg, bias);
    k_softmax<<<BATCH, 256>>>(norm1);
    k_pool<<<dim3(3, 8, BATCH), 256>>>(trg);
    k_red<<<(BATCH * KDIM) / 256, 256>>>();
    k_out<<<dim3(HID / 8, BATCH), 256>>>(bias, summ);
}